// round 10
// baseline (speedup 1.0000x reference)
#include <cuda_runtime.h>
#include <cuda_bf16.h>
#include <cuda_fp16.h>
#include <cstdint>

// Problem constants (from reference)
#define NN      50000
#define EE      800000
#define FD      128
#define GG      64
#define OUTD    64
#define NEXP    3
#define TEMP_F  101.0f

// HMMA MoE config: padded bf16 images, 128 rows x 136 cols (stride 272B)
#define IMG_ELEMS 17408            // 128*136
#define IMG_B     34816            // bytes per image
#define ROWSTRIDE 272              // bytes per row
#define MOE_SMEM  (6 * IMG_B + 1536)   // Ah Al | Bbuf0(hi,lo) Bbuf1(hi,lo) | bias[384]

#define SCAN_B    1024
#define SCAN_NBLK 64               // covers up to 65536 nodes

// ---------------- device scratch (no cudaMalloc allowed) ----------------
__device__ float g_dinv[NN];
__device__ int   g_degE[NN];          // in-edge count (no self loop)
__device__ int   g_fill[NN];
__device__ int   g_off[NN + 1];       // CSR row offsets
__device__ int   g_csr[EE];           // CSR src indices
__device__ int   g_bsum[SCAN_NBLK];   // per-block sums for scan
__device__ float g_gate0[NN * NEXP];
__device__ float g_gate1[NN * NEXP];
__device__ float g_bufA[NN * FD];     // fp32 aggregated features (moe input)
__device__ float g_bufB[NN * FD];     // fp32 layer-1 output (pool input)
__device__ __half g_hh[NN * FD];      // fp16 gather image (x, then h1)
__device__ int   g_is64;
// Pre-split weights: [layer(2)][expert(3)][hi,lo][128*136] bf16 (padded row-major [n][k])
__device__ __nv_bfloat16 g_wprep[2 * 3 * 2 * IMG_ELEMS];

// ---------------- helpers ----------------
__device__ __forceinline__ uint32_t smem_u32(const void* p) {
    uint32_t a;
    asm("{ .reg .u64 t; cvta.to.shared.u64 t, %1; cvt.u32.u64 %0, t; }" : "=r"(a) : "l"(p));
    return a;
}
__device__ __forceinline__ int load_idx(const void* p, long long i) {
    if (g_is64) return (int)((const long long*)p)[i];
    return ((const int*)p)[i];
}
__device__ __forceinline__ void cpa16(uint32_t dst, const void* src) {
    asm volatile("cp.async.cg.shared.global [%0], [%1], 16;" :: "r"(dst), "l"(src) : "memory");
}
#define CP_COMMIT() asm volatile("cp.async.commit_group;" ::: "memory")
#define CP_WAIT0()  asm volatile("cp.async.wait_group 0;" ::: "memory")

__device__ __forceinline__ void ldsm_x4(uint32_t (&r)[4], uint32_t addr) {
    asm volatile("ldmatrix.sync.aligned.m8n8.x4.shared.b16 {%0,%1,%2,%3}, [%4];"
                 : "=r"(r[0]), "=r"(r[1]), "=r"(r[2]), "=r"(r[3]) : "r"(addr));
}
__device__ __forceinline__ void ldsm_x2(uint32_t (&r)[2], uint32_t addr) {
    asm volatile("ldmatrix.sync.aligned.m8n8.x2.shared.b16 {%0,%1}, [%2];"
                 : "=r"(r[0]), "=r"(r[1]) : "r"(addr));
}
__device__ __forceinline__ void mma_bf16(float (&c)[4], const uint32_t (&a)[4],
                                         const uint32_t (&b)[2]) {
    asm volatile("mma.sync.aligned.m16n8k16.row.col.f32.bf16.bf16.f32 "
                 "{%0,%1,%2,%3}, {%4,%5,%6,%7}, {%8,%9}, {%0,%1,%2,%3};"
                 : "+f"(c[0]), "+f"(c[1]), "+f"(c[2]), "+f"(c[3])
                 : "r"(a[0]), "r"(a[1]), "r"(a[2]), "r"(a[3]), "r"(b[0]), "r"(b[1]));
}
__device__ __forceinline__ float4 h4_to_f4(uint2 u) {
    __half2 a = *reinterpret_cast<__half2*>(&u.x);
    __half2 b = *reinterpret_cast<__half2*>(&u.y);
    float2 fa = __half22float2(a), fb = __half22float2(b);
    return make_float4(fa.x, fa.y, fb.x, fb.y);
}

// ---------------- fused prep0: deg zero | weight split | detect | x->fp16 ----------------
// Blocks [0,nbn): zero deg/fill (+detect). [nbn,nbn+6): wprep. [nbn+6, ...): x->fp16.
__global__ void prep0_kernel(const int* eip, const float* __restrict__ x,
                             const float* __restrict__ W0,
                             const float* __restrict__ W1, int n, int nbn) {
    if ((int)blockIdx.x < nbn) {
        int i = blockIdx.x * blockDim.x + threadIdx.x;
        if (i < n) { g_degE[i] = 0; g_fill[i] = 0; }
        if (blockIdx.x == 0 && threadIdx.x == 0) {
            int all0 = 1;
            #pragma unroll
            for (int k = 1; k < 128; k += 2) if (eip[k] != 0) all0 = 0;
            g_is64 = all0;
        }
        return;
    }
    if ((int)blockIdx.x < nbn + 6) {
        int b = blockIdx.x - nbn;                   // 0..5 = layer*3+expert
        const float* src = (b < 3 ? W0 : W1) + (b % 3) * (FD * FD);
        __nv_bfloat16* dhi = g_wprep + (size_t)b * 2 * IMG_ELEMS;
        __nv_bfloat16* dlo = dhi + IMG_ELEMS;
        for (int i = threadIdx.x; i < FD * FD; i += blockDim.x) {
            int nidx = i >> 7, k = i & 127;
            float v = src[k * FD + nidx];
            __nv_bfloat16 h = __float2bfloat16(v);
            __nv_bfloat16 l = __float2bfloat16(v - __bfloat162float(h));
            dhi[nidx * 136 + k] = h;
            dlo[nidx * 136 + k] = l;
        }
        return;
    }
    // x -> fp16 image
    int id = (blockIdx.x - nbn - 6) * blockDim.x + threadIdx.x;  // float4 index
    if (id < n * 32) {
        float4 v = reinterpret_cast<const float4*>(x)[id];
        uint2 u;
        *reinterpret_cast<__half2*>(&u.x) = __floats2half2_rn(v.x, v.y);
        *reinterpret_cast<__half2*>(&u.y) = __floats2half2_rn(v.z, v.w);
        reinterpret_cast<uint2*>(g_hh)[id] = u;
    }
}

__global__ void deg_count_kernel(const void* ei, int E) {
    int i = blockIdx.x * blockDim.x + threadIdx.x;
    if (i >= E) return;
    atomicAdd(&g_degE[load_idx(ei, (long long)E + i)], 1);
}

// ---- scan phase 1: per-block sums ----
__global__ void __launch_bounds__(SCAN_B, 1) scan_reduce_kernel(int n) {
    __shared__ int sred[32];
    int i = blockIdx.x * SCAN_B + threadIdx.x;
    int v = (i < n) ? g_degE[i] : 0;
    #pragma unroll
    for (int o = 16; o > 0; o >>= 1) v += __shfl_down_sync(0xFFFFFFFFu, v, o);
    if ((threadIdx.x & 31) == 0) sred[threadIdx.x >> 5] = v;
    __syncthreads();
    if (threadIdx.x < 32) {
        int w = (threadIdx.x < SCAN_B / 32) ? sred[threadIdx.x] : 0;
        #pragma unroll
        for (int o = 16; o > 0; o >>= 1) w += __shfl_down_sync(0xFFFFFFFFu, w, o);
        if (threadIdx.x == 0) g_bsum[blockIdx.x] = w;
    }
}

// ---- scan phase 2 (fat): block-sum scan + elementwise scan + dinv + gates ----
__global__ void __launch_bounds__(SCAN_B, 1)
scan_apply_kernel(const float* __restrict__ top, const float* __restrict__ Wg0,
                  const float* __restrict__ Wg1, int n, int nblk) {
    __shared__ int swarp[32];
    __shared__ int sbs[SCAN_NBLK];
    const int t = threadIdx.x;
    if (t < SCAN_NBLK) sbs[t] = (t < nblk) ? g_bsum[t] : 0;
    __syncthreads();
    #pragma unroll
    for (int o = 1; o < SCAN_NBLK; o <<= 1) {
        int u = (t >= o && t < SCAN_NBLK) ? sbs[t - o] : 0;
        __syncthreads();
        if (t < SCAN_NBLK) sbs[t] += u;
        __syncthreads();
    }
    const int blockbase = (blockIdx.x == 0) ? 0 : sbs[blockIdx.x - 1];

    int i = blockIdx.x * SCAN_B + t;
    int lane = t & 31, wid = t >> 5;
    int v = (i < n) ? g_degE[i] : 0;
    int inc = v;
    #pragma unroll
    for (int o = 1; o < 32; o <<= 1) {
        int u = __shfl_up_sync(0xFFFFFFFFu, inc, o);
        if (lane >= o) inc += u;
    }
    if (lane == 31) swarp[wid] = inc;
    __syncthreads();
    if (wid == 0) {
        int w = (lane < SCAN_B / 32) ? swarp[lane] : 0;
        int winc = w;
        #pragma unroll
        for (int o = 1; o < 32; o <<= 1) {
            int u = __shfl_up_sync(0xFFFFFFFFu, winc, o);
            if (lane >= o) winc += u;
        }
        swarp[lane] = winc - w;
    }
    __syncthreads();
    int base = blockbase + swarp[wid];
    if (i < n) {
        g_off[i] = base + inc - v;
        if (i == n - 1) g_off[n] = base + inc;

        g_dinv[i] = rsqrtf((float)(v + 1));
        float t0 = top[i * 4 + 0], t1 = top[i * 4 + 1];
        float t2 = top[i * 4 + 2], t3 = top[i * 4 + 3];
        const float* wgs[2] = {Wg0, Wg1};
        float* outs[2] = {g_gate0, g_gate1};
        #pragma unroll
        for (int L = 0; L < 2; L++) {
            const float* Wg = wgs[L];
            float l[NEXP];
            #pragma unroll
            for (int e = 0; e < NEXP; e++)
                l[e] = (t0 * Wg[e * 4 + 0] + t1 * Wg[e * 4 + 1] +
                        t2 * Wg[e * 4 + 2] + t3 * Wg[e * 4 + 3]) * (1.0f / TEMP_F);
            float m = fmaxf(l[0], fmaxf(l[1], l[2]));
            float e0 = __expf(l[0] - m), e1 = __expf(l[1] - m), e2 = __expf(l[2] - m);
            float inv = 1.0f / (e0 + e1 + e2);
            outs[L][i * 3 + 0] = e0 * inv;
            outs[L][i * 3 + 1] = e1 * inv;
            outs[L][i * 3 + 2] = e2 * inv;
        }
    }
}

__global__ void scatter_kernel(const void* ei, int E) {
    int i = blockIdx.x * blockDim.x + threadIdx.x;
    if (i >= E) return;
    int s = load_idx(ei, i);
    int d = load_idx(ei, (long long)E + i);
    int pos = g_off[d] + atomicAdd(&g_fill[d], 1);
    g_csr[pos] = s;
}

// ---------------- CSR aggregation from fp16 image (no atomics) ----------------
// out[r,:] = dinv[r]^2*h[r,:] + sum dinv[r]*dinv[s]*h[s,:], h in fp16, acc fp32.
__global__ void agg_csr_half_kernel(const __half* __restrict__ hhv,
                                    float* __restrict__ out, int n) {
    int r = (blockIdx.x * blockDim.x + threadIdx.x) >> 5;
    int lane = threadIdx.x & 31;
    if (r >= n) return;
    const uint2* hp = (const uint2*)hhv;     // 4 halves per uint2; 32 per row
    float di = g_dinv[r];
    float4 self = h4_to_f4(hp[(size_t)r * 32 + lane]);
    float s2 = di * di;
    float4 acc = make_float4(s2 * self.x, s2 * self.y, s2 * self.z, s2 * self.w);
    int e = g_off[r], e1 = g_off[r + 1];
    for (; e + 2 <= e1; e += 2) {
        int s0 = g_csr[e], s1 = g_csr[e + 1];
        float n0 = di * g_dinv[s0], n1 = di * g_dinv[s1];
        float4 v0 = h4_to_f4(hp[(size_t)s0 * 32 + lane]);
        float4 v1 = h4_to_f4(hp[(size_t)s1 * 32 + lane]);
        acc.x = fmaf(n0, v0.x, fmaf(n1, v1.x, acc.x));
        acc.y = fmaf(n0, v0.y, fmaf(n1, v1.y, acc.y));
        acc.z = fmaf(n0, v0.z, fmaf(n1, v1.z, acc.z));
        acc.w = fmaf(n0, v0.w, fmaf(n1, v1.w, acc.w));
    }
    if (e < e1) {
        int s0 = g_csr[e];
        float n0 = di * g_dinv[s0];
        float4 v0 = h4_to_f4(hp[(size_t)s0 * 32 + lane]);
        acc.x = fmaf(n0, v0.x, acc.x);
        acc.y = fmaf(n0, v0.y, acc.y);
        acc.z = fmaf(n0, v0.z, acc.z);
        acc.w = fmaf(n0, v0.w, acc.w);
    }
    ((float4*)out)[(size_t)r * 32 + lane] = acc;
}

// ---------------- HMMA MoE layer ----------------
// Writes fp32 out (if non-null) and/or fp16 outh (if non-null).
__global__ void __launch_bounds__(256, 1)
moe_hmma_kernel(const float* __restrict__ A, const __nv_bfloat16* __restrict__ wprepL,
                const float* __restrict__ bias, const float* __restrict__ gate,
                float* __restrict__ out, __half* __restrict__ outh, int n)
{
    extern __shared__ char smem[];
    const uint32_t sb = smem_u32(smem);
    const int t = threadIdx.x, lane = t & 31, wid = t >> 5;
    const int row0 = blockIdx.x * 128;
    float* sBias = (float*)(smem + 6 * IMG_B);

    for (int i = t; i < NEXP * FD; i += 256) sBias[i] = bias[i];

    #pragma unroll
    for (int i = 0; i < 16; i++) {
        int id = i * 256 + t;
        int r = id >> 5, c4 = id & 31, k0 = c4 * 4;
        int gr = row0 + r;
        float4 v = make_float4(0.f, 0.f, 0.f, 0.f);
        if (gr < n) v = reinterpret_cast<const float4*>(A)[(size_t)gr * 32 + c4];
        float vv[4] = {v.x, v.y, v.z, v.w};
        __nv_bfloat16 h[4], l[4];
        #pragma unroll
        for (int j = 0; j < 4; j++) {
            h[j] = __float2bfloat16(vv[j]);
            l[j] = __float2bfloat16(vv[j] - __bfloat162float(h[j]));
        }
        *(uint64_t*)(smem + r * ROWSTRIDE + k0 * 2)         = *(const uint64_t*)h;
        *(uint64_t*)(smem + IMG_B + r * ROWSTRIDE + k0 * 2) = *(const uint64_t*)l;
    }

    {
        uint32_t dst = sb + 2 * IMG_B;
        const char* src = (const char*)wprepL;
        for (int i = t; i < 2 * IMG_B / 16; i += 256) cpa16(dst + i * 16, src + i * 16);
        CP_COMMIT();
    }
    __syncthreads();
    CP_WAIT0();
    __syncthreads();

    const int m0 = (wid & 3) * 32, n0 = (wid >> 2) * 64;
    uint32_t aoff[2];
    #pragma unroll
    for (int mt = 0; mt < 2; mt++)
        aoff[mt] = (uint32_t)((m0 + mt * 16 + (lane & 7) + ((lane >> 3) & 1) * 8) * ROWSTRIDE
                              + (lane >> 4) * 16);
    const int l16 = lane & 15;
    uint32_t boff[8];
    #pragma unroll
    for (int nt = 0; nt < 8; nt++)
        boff[nt] = (uint32_t)((n0 + nt * 8 + (l16 & 7)) * ROWSTRIDE + (l16 >> 3) * 16);

    float o[2][8][4];
    #pragma unroll
    for (int mt = 0; mt < 2; mt++)
        #pragma unroll
        for (int nt = 0; nt < 8; nt++)
            #pragma unroll
            for (int j = 0; j < 4; j++) o[mt][nt][j] = 0.f;

    for (int e = 0; e < NEXP; e++) {
        const uint32_t bbase = sb + 2 * IMG_B + (uint32_t)(e & 1) * 2 * IMG_B;
        if (e < 2) {
            uint32_t dst = sb + 2 * IMG_B + (uint32_t)((e + 1) & 1) * 2 * IMG_B;
            const char* src = (const char*)(wprepL + (size_t)(e + 1) * 2 * IMG_ELEMS);
            for (int i = t; i < 2 * IMG_B / 16; i += 256) cpa16(dst + i * 16, src + i * 16);
            CP_COMMIT();
        }

        float c[2][8][4];
        #pragma unroll
        for (int mt = 0; mt < 2; mt++)
            #pragma unroll
            for (int nt = 0; nt < 8; nt++)
                #pragma unroll
                for (int j = 0; j < 4; j++) c[mt][nt][j] = 0.f;

        #pragma unroll 4
        for (int ks = 0; ks < 24; ks++) {
            int term = ks >> 3;
            uint32_t kb = (uint32_t)((ks & 7) * 32);
            uint32_t abase = sb + (term == 1 ? IMG_B : 0u) + kb;
            uint32_t bbs   = bbase + (term == 2 ? IMG_B : 0u) + kb;
            uint32_t a[2][4], b[8][2];
            #pragma unroll
            for (int mt = 0; mt < 2; mt++) ldsm_x4(a[mt], abase + aoff[mt]);
            #pragma unroll
            for (int nt = 0; nt < 8; nt++) ldsm_x2(b[nt], bbs + boff[nt]);
            #pragma unroll
            for (int mt = 0; mt < 2; mt++)
                #pragma unroll
                for (int nt = 0; nt < 8; nt++) mma_bf16(c[mt][nt], a[mt], b[nt]);
        }

        #pragma unroll
        for (int mt = 0; mt < 2; mt++) {
            int r0 = row0 + m0 + mt * 16 + (lane >> 2);
            int r1 = r0 + 8;
            float g0 = (r0 < n) ? gate[r0 * 3 + e] : 0.f;
            float g1 = (r1 < n) ? gate[r1 * 3 + e] : 0.f;
            #pragma unroll
            for (int nt = 0; nt < 8; nt++) {
                int nc = n0 + nt * 8 + 2 * (lane & 3);
                float b0v = sBias[e * 128 + nc], b1v = sBias[e * 128 + nc + 1];
                o[mt][nt][0] = fmaf(g0, fmaxf(c[mt][nt][0] + b0v, 0.f), o[mt][nt][0]);
                o[mt][nt][1] = fmaf(g0, fmaxf(c[mt][nt][1] + b1v, 0.f), o[mt][nt][1]);
                o[mt][nt][2] = fmaf(g1, fmaxf(c[mt][nt][2] + b0v, 0.f), o[mt][nt][2]);
                o[mt][nt][3] = fmaf(g1, fmaxf(c[mt][nt][3] + b1v, 0.f), o[mt][nt][3]);
            }
        }
        if (e < 2) CP_WAIT0();
        __syncthreads();
    }

    #pragma unroll
    for (int mt = 0; mt < 2; mt++) {
        int r0 = row0 + m0 + mt * 16 + (lane >> 2);
        int r1 = r0 + 8;
        #pragma unroll
        for (int nt = 0; nt < 8; nt++) {
            int nc = n0 + nt * 8 + 2 * (lane & 3);
            if (r0 < n) {
                if (out)
                    *(float2*)(out + (size_t)r0 * 128 + nc) = make_float2(o[mt][nt][0], o[mt][nt][1]);
                if (outh)
                    *(__half2*)(outh + (size_t)r0 * 128 + nc) = __floats2half2_rn(o[mt][nt][0], o[mt][nt][1]);
            }
            if (r1 < n) {
                if (out)
                    *(float2*)(out + (size_t)r1 * 128 + nc) = make_float2(o[mt][nt][2], o[mt][nt][3]);
                if (outh)
                    *(__half2*)(outh + (size_t)r1 * 128 + nc) = __floats2half2_rn(o[mt][nt][2], o[mt][nt][3]);
            }
        }
    }
}

// ---------------- fused pool + final (batch is sorted) ----------------
__device__ __forceinline__ int lbound_batch(const void* b, int n, long long key) {
    int lo = 0, hi = n;
    while (lo < hi) {
        int m = (lo + hi) >> 1;
        long long v = g_is64 ? ((const long long*)b)[m] : (long long)((const int*)b)[m];
        if (v < key) lo = m + 1; else hi = m;
    }
    return lo;
}

__global__ void pool_final_kernel(const float* __restrict__ h, const void* batch,
                                  const float* __restrict__ Wf,
                                  const float* __restrict__ bf,
                                  float* __restrict__ outp, int n) {
    __shared__ float sp[128];
    __shared__ int sLo, sHi;
    const int g = blockIdx.x, t = threadIdx.x;
    if (t == 0) sLo = lbound_batch(batch, n, g);
    if (t == 1) sHi = lbound_batch(batch, n, g + 1);
    __syncthreads();
    const int lo = sLo, hi = sHi;
    float s = 0.f;
    int r = lo;
    for (; r + 4 <= hi; r += 4) {
        s += h[(size_t)r * 128 + t] + h[(size_t)(r + 1) * 128 + t] +
             h[(size_t)(r + 2) * 128 + t] + h[(size_t)(r + 3) * 128 + t];
    }
    for (; r < hi; r++) s += h[(size_t)r * 128 + t];
    sp[t] = s / fmaxf((float)(hi - lo), 1.0f);
    __syncthreads();
    if (t < OUTD) {
        float acc = bf[t];
        #pragma unroll
        for (int k = 0; k < 128; k++) acc = fmaf(sp[k], Wf[k * OUTD + t], acc);
        outp[g * OUTD + t] = acc;
    }
}

// ---------------- launcher ----------------
extern "C" void kernel_launch(void* const* d_in, const int* in_sizes, int n_in,
                              void* d_out, int out_size) {
    const float* x    = (const float*)d_in[0];
    const float* top  = (const float*)d_in[1];
    const void*  ei   = d_in[2];
    const void*  batch= d_in[3];
    const float* W0   = (const float*)d_in[4];
    const float* b0   = (const float*)d_in[5];
    const float* Wg0  = (const float*)d_in[6];
    const float* W1   = (const float*)d_in[7];
    const float* b1   = (const float*)d_in[8];
    const float* Wg1  = (const float*)d_in[9];
    const float* Wf   = (const float*)d_in[10];
    const float* bf   = (const float*)d_in[11];
    float* out = (float*)d_out;

    const int N = in_sizes[0] / FD;
    const int E = in_sizes[2] / 2;

    // Device addresses for symbols passed as kernel args (R1 lesson: ATS makes
    // host-shadow symbol reads silently return host zeros).
    float* bufA;  cudaGetSymbolAddress((void**)&bufA,  g_bufA);
    float* bufB;  cudaGetSymbolAddress((void**)&bufB,  g_bufB);
    float* gate0; cudaGetSymbolAddress((void**)&gate0, g_gate0);
    float* gate1; cudaGetSymbolAddress((void**)&gate1, g_gate1);
    __half* hh;   cudaGetSymbolAddress((void**)&hh,    g_hh);
    __nv_bfloat16* wprep; cudaGetSymbolAddress((void**)&wprep, g_wprep);

    cudaFuncSetAttribute(moe_hmma_kernel, cudaFuncAttributeMaxDynamicSharedMemorySize, MOE_SMEM);

    const int TPB = 256;
    int nb_n    = (N + TPB - 1) / TPB;
    int nb_e    = (E + TPB - 1) / TPB;
    int nb_aw   = (N * 32 + TPB - 1) / TPB;   // warp per row
    int nb_moe  = (N + 127) / 128;
    int nb_scan = (N + SCAN_B - 1) / SCAN_B;  // <= SCAN_NBLK
    int nb_x    = (N * 32 + TPB - 1) / TPB;   // x->fp16 conversion blocks

    // fused prep: zero degrees | split weights | detect idx width | x->fp16
    prep0_kernel<<<nb_n + 6 + nb_x, TPB>>>((const int*)ei, x, W0, W1, N, nb_n);
    deg_count_kernel<<<nb_e, TPB>>>(ei, E);
    scan_reduce_kernel<<<nb_scan, SCAN_B>>>(N);
    scan_apply_kernel<<<nb_scan, SCAN_B>>>(top, Wg0, Wg1, N, nb_scan);  // + dinv + gates
    scatter_kernel<<<nb_e, TPB>>>(ei, E);

    // layer 0: agg from fp16 x-image; moe emits fp16 image only (feeds layer-1 agg)
    agg_csr_half_kernel<<<nb_aw, TPB>>>(hh, bufA, N);
    moe_hmma_kernel<<<nb_moe, TPB, MOE_SMEM>>>(bufA, wprep, b0, gate0, nullptr, hh, N);
    // layer 1: agg from fp16 h1-image; moe emits fp32 (feeds pooling)
    agg_csr_half_kernel<<<nb_aw, TPB>>>(hh, bufA, N);
    moe_hmma_kernel<<<nb_moe, TPB, MOE_SMEM>>>(bufA, wprep + 3 * 2 * IMG_ELEMS, b1, gate1,
                                               bufB, nullptr, N);

    // fused pooling + final projection
    pool_final_kernel<<<GG, 128>>>(bufB, batch, Wf, bf, out, N);
}

// round 11
// speedup vs baseline: 1.1678x; 1.1678x over previous
#include <cuda_runtime.h>
#include <cuda_fp16.h>
#include <cstdint>

// Problem constants (from reference)
#define NN      50000
#define EE      800000
#define FD      128
#define GG      64
#define OUTD    64
#define NEXP    3
#define TEMP_F  101.0f

// HMMA MoE config: padded fp16 images, 128 rows x 136 cols (stride 272B)
#define IMG_ELEMS 17408            // 128*136
#define IMG_B     34816            // bytes per image
#define ROWSTRIDE 272              // bytes per row
// smem: A(1 img) | Bbuf0(hi,lo) | Bbuf1(hi,lo) | bias[384]
#define MOE_SMEM  (5 * IMG_B + 1536)

#define SCAN_B    1024
#define SCAN_NBLK 64               // covers up to 65536 nodes

// ---------------- device scratch (no cudaMalloc allowed) ----------------
__device__ float g_dinv[NN];
__device__ int   g_degE[NN];          // in-edge count (no self loop)
__device__ int   g_fill[NN];
__device__ int   g_off[NN + 1];       // CSR row offsets
__device__ int   g_csr[EE];           // CSR src indices
__device__ int   g_bsum[SCAN_NBLK];   // per-block sums for scan
__device__ float g_gate0[NN * NEXP];
__device__ float g_gate1[NN * NEXP];
__device__ __half g_ah[NN * FD];      // fp16 aggregated features (moe A input)
__device__ float g_bufB[NN * FD];     // fp32 layer-1 output (pool input)
__device__ __half g_hh[NN * FD];      // fp16 gather image (x, then h1)
__device__ int   g_is64;
// Pre-split fp16 weights: [layer(2)][expert(3)][hi,lo][128*136] (padded row-major [n][k])
__device__ __half g_wprep[2 * 3 * 2 * IMG_ELEMS];

// ---------------- helpers ----------------
__device__ __forceinline__ uint32_t smem_u32(const void* p) {
    uint32_t a;
    asm("{ .reg .u64 t; cvta.to.shared.u64 t, %1; cvt.u32.u64 %0, t; }" : "=r"(a) : "l"(p));
    return a;
}
__device__ __forceinline__ int load_idx(const void* p, long long i) {
    if (g_is64) return (int)((const long long*)p)[i];
    return ((const int*)p)[i];
}
__device__ __forceinline__ void cpa16(uint32_t dst, const void* src) {
    asm volatile("cp.async.cg.shared.global [%0], [%1], 16;" :: "r"(dst), "l"(src) : "memory");
}
// cp.async with runtime src-size (0 => full zero-fill)
__device__ __forceinline__ void cpa16z(uint32_t dst, const void* src, int sz) {
    asm volatile("cp.async.cg.shared.global [%0], [%1], 16, %2;"
                 :: "r"(dst), "l"(src), "r"(sz) : "memory");
}
#define CP_COMMIT() asm volatile("cp.async.commit_group;" ::: "memory")
#define CP_WAIT0()  asm volatile("cp.async.wait_group 0;" ::: "memory")

__device__ __forceinline__ void ldsm_x4(uint32_t (&r)[4], uint32_t addr) {
    asm volatile("ldmatrix.sync.aligned.m8n8.x4.shared.b16 {%0,%1,%2,%3}, [%4];"
                 : "=r"(r[0]), "=r"(r[1]), "=r"(r[2]), "=r"(r[3]) : "r"(addr));
}
__device__ __forceinline__ void ldsm_x2(uint32_t (&r)[2], uint32_t addr) {
    asm volatile("ldmatrix.sync.aligned.m8n8.x2.shared.b16 {%0,%1}, [%2];"
                 : "=r"(r[0]), "=r"(r[1]) : "r"(addr));
}
__device__ __forceinline__ void mma_f16(float (&c)[4], const uint32_t (&a)[4],
                                        const uint32_t (&b)[2]) {
    asm volatile("mma.sync.aligned.m16n8k16.row.col.f32.f16.f16.f32 "
                 "{%0,%1,%2,%3}, {%4,%5,%6,%7}, {%8,%9}, {%0,%1,%2,%3};"
                 : "+f"(c[0]), "+f"(c[1]), "+f"(c[2]), "+f"(c[3])
                 : "r"(a[0]), "r"(a[1]), "r"(a[2]), "r"(a[3]), "r"(b[0]), "r"(b[1]));
}
__device__ __forceinline__ float4 h4_to_f4(uint2 u) {
    __half2 a = *reinterpret_cast<__half2*>(&u.x);
    __half2 b = *reinterpret_cast<__half2*>(&u.y);
    float2 fa = __half22float2(a), fb = __half22float2(b);
    return make_float4(fa.x, fa.y, fb.x, fb.y);
}

// ---------------- fused prep0: deg zero | weight split(fp16) | detect | x->fp16 ----------------
__global__ void prep0_kernel(const int* eip, const float* __restrict__ x,
                             const float* __restrict__ W0,
                             const float* __restrict__ W1, int n, int nbn) {
    if ((int)blockIdx.x < nbn) {
        int i = blockIdx.x * blockDim.x + threadIdx.x;
        if (i < n) { g_degE[i] = 0; g_fill[i] = 0; }
        if (blockIdx.x == 0 && threadIdx.x == 0) {
            int all0 = 1;
            #pragma unroll
            for (int k = 1; k < 128; k += 2) if (eip[k] != 0) all0 = 0;
            g_is64 = all0;
        }
        return;
    }
    if ((int)blockIdx.x < nbn + 6) {
        int b = blockIdx.x - nbn;                   // 0..5 = layer*3+expert
        const float* src = (b < 3 ? W0 : W1) + (b % 3) * (FD * FD);
        __half* dhi = g_wprep + (size_t)b * 2 * IMG_ELEMS;
        __half* dlo = dhi + IMG_ELEMS;
        for (int i = threadIdx.x; i < FD * FD; i += blockDim.x) {
            int nidx = i >> 7, k = i & 127;
            float v = src[k * FD + nidx];
            __half h = __float2half_rn(v);
            __half l = __float2half_rn(v - __half2float(h));
            dhi[nidx * 136 + k] = h;
            dlo[nidx * 136 + k] = l;
        }
        return;
    }
    // x -> fp16 gather image
    int id = (blockIdx.x - nbn - 6) * blockDim.x + threadIdx.x;  // float4 index
    if (id < n * 32) {
        float4 v = reinterpret_cast<const float4*>(x)[id];
        uint2 u;
        *reinterpret_cast<__half2*>(&u.x) = __floats2half2_rn(v.x, v.y);
        *reinterpret_cast<__half2*>(&u.y) = __floats2half2_rn(v.z, v.w);
        reinterpret_cast<uint2*>(g_hh)[id] = u;
    }
}

__global__ void deg_count_kernel(const void* ei, int E) {
    int i = blockIdx.x * blockDim.x + threadIdx.x;
    if (i >= E) return;
    atomicAdd(&g_degE[load_idx(ei, (long long)E + i)], 1);
}

// ---- scan phase 1: per-block sums ----
__global__ void __launch_bounds__(SCAN_B, 1) scan_reduce_kernel(int n) {
    __shared__ int sred[32];
    int i = blockIdx.x * SCAN_B + threadIdx.x;
    int v = (i < n) ? g_degE[i] : 0;
    #pragma unroll
    for (int o = 16; o > 0; o >>= 1) v += __shfl_down_sync(0xFFFFFFFFu, v, o);
    if ((threadIdx.x & 31) == 0) sred[threadIdx.x >> 5] = v;
    __syncthreads();
    if (threadIdx.x < 32) {
        int w = (threadIdx.x < SCAN_B / 32) ? sred[threadIdx.x] : 0;
        #pragma unroll
        for (int o = 16; o > 0; o >>= 1) w += __shfl_down_sync(0xFFFFFFFFu, w, o);
        if (threadIdx.x == 0) g_bsum[blockIdx.x] = w;
    }
}

// ---- scan phase 2 (fat): block-sum scan + elementwise scan + dinv + gates ----
__global__ void __launch_bounds__(SCAN_B, 1)
scan_apply_kernel(const float* __restrict__ top, const float* __restrict__ Wg0,
                  const float* __restrict__ Wg1, int n, int nblk) {
    __shared__ int swarp[32];
    __shared__ int sbs[SCAN_NBLK];
    const int t = threadIdx.x;
    if (t < SCAN_NBLK) sbs[t] = (t < nblk) ? g_bsum[t] : 0;
    __syncthreads();
    #pragma unroll
    for (int o = 1; o < SCAN_NBLK; o <<= 1) {
        int u = (t >= o && t < SCAN_NBLK) ? sbs[t - o] : 0;
        __syncthreads();
        if (t < SCAN_NBLK) sbs[t] += u;
        __syncthreads();
    }
    const int blockbase = (blockIdx.x == 0) ? 0 : sbs[blockIdx.x - 1];

    int i = blockIdx.x * SCAN_B + t;
    int lane = t & 31, wid = t >> 5;
    int v = (i < n) ? g_degE[i] : 0;
    int inc = v;
    #pragma unroll
    for (int o = 1; o < 32; o <<= 1) {
        int u = __shfl_up_sync(0xFFFFFFFFu, inc, o);
        if (lane >= o) inc += u;
    }
    if (lane == 31) swarp[wid] = inc;
    __syncthreads();
    if (wid == 0) {
        int w = (lane < SCAN_B / 32) ? swarp[lane] : 0;
        int winc = w;
        #pragma unroll
        for (int o = 1; o < 32; o <<= 1) {
            int u = __shfl_up_sync(0xFFFFFFFFu, winc, o);
            if (lane >= o) winc += u;
        }
        swarp[lane] = winc - w;
    }
    __syncthreads();
    int base = blockbase + swarp[wid];
    if (i < n) {
        g_off[i] = base + inc - v;
        if (i == n - 1) g_off[n] = base + inc;

        g_dinv[i] = rsqrtf((float)(v + 1));
        float t0 = top[i * 4 + 0], t1 = top[i * 4 + 1];
        float t2 = top[i * 4 + 2], t3 = top[i * 4 + 3];
        const float* wgs[2] = {Wg0, Wg1};
        float* outs[2] = {g_gate0, g_gate1};
        #pragma unroll
        for (int L = 0; L < 2; L++) {
            const float* Wg = wgs[L];
            float l[NEXP];
            #pragma unroll
            for (int e = 0; e < NEXP; e++)
                l[e] = (t0 * Wg[e * 4 + 0] + t1 * Wg[e * 4 + 1] +
                        t2 * Wg[e * 4 + 2] + t3 * Wg[e * 4 + 3]) * (1.0f / TEMP_F);
            float m = fmaxf(l[0], fmaxf(l[1], l[2]));
            float e0 = __expf(l[0] - m), e1 = __expf(l[1] - m), e2 = __expf(l[2] - m);
            float inv = 1.0f / (e0 + e1 + e2);
            outs[L][i * 3 + 0] = e0 * inv;
            outs[L][i * 3 + 1] = e1 * inv;
            outs[L][i * 3 + 2] = e2 * inv;
        }
    }
}

__global__ void scatter_kernel(const void* ei, int E) {
    int i = blockIdx.x * blockDim.x + threadIdx.x;
    if (i >= E) return;
    int s = load_idx(ei, i);
    int d = load_idx(ei, (long long)E + i);
    int pos = g_off[d] + atomicAdd(&g_fill[d], 1);
    g_csr[pos] = s;
}

// ---------------- CSR aggregation from fp16 image (no atomics), fp16 out ----------------
__global__ void agg_csr_half_kernel(const __half* __restrict__ hhv,
                                    __half* __restrict__ out, int n) {
    int r = (blockIdx.x * blockDim.x + threadIdx.x) >> 5;
    int lane = threadIdx.x & 31;
    if (r >= n) return;
    const uint2* hp = (const uint2*)hhv;     // 4 halves per uint2; 32 per row
    float di = g_dinv[r];
    float4 self = h4_to_f4(hp[(size_t)r * 32 + lane]);
    float s2 = di * di;
    float4 acc = make_float4(s2 * self.x, s2 * self.y, s2 * self.z, s2 * self.w);
    int e = g_off[r], e1 = g_off[r + 1];
    for (; e + 2 <= e1; e += 2) {
        int s0 = g_csr[e], s1 = g_csr[e + 1];
        float n0 = di * g_dinv[s0], n1 = di * g_dinv[s1];
        float4 v0 = h4_to_f4(hp[(size_t)s0 * 32 + lane]);
        float4 v1 = h4_to_f4(hp[(size_t)s1 * 32 + lane]);
        acc.x = fmaf(n0, v0.x, fmaf(n1, v1.x, acc.x));
        acc.y = fmaf(n0, v0.y, fmaf(n1, v1.y, acc.y));
        acc.z = fmaf(n0, v0.z, fmaf(n1, v1.z, acc.z));
        acc.w = fmaf(n0, v0.w, fmaf(n1, v1.w, acc.w));
    }
    if (e < e1) {
        int s0 = g_csr[e];
        float n0 = di * g_dinv[s0];
        float4 v0 = h4_to_f4(hp[(size_t)s0 * 32 + lane]);
        acc.x = fmaf(n0, v0.x, acc.x);
        acc.y = fmaf(n0, v0.y, acc.y);
        acc.z = fmaf(n0, v0.z, acc.z);
        acc.w = fmaf(n0, v0.w, acc.w);
    }
    uint2 uo;
    *reinterpret_cast<__half2*>(&uo.x) = __floats2half2_rn(acc.x, acc.y);
    *reinterpret_cast<__half2*>(&uo.y) = __floats2half2_rn(acc.z, acc.w);
    ((uint2*)out)[(size_t)r * 32 + lane] = uo;
}

// ---------------- HMMA MoE layer: fp16 A (single), fp16 W (hi/lo split) ----------------
// out[m,:] = sum_e gate[m,e]*relu(A[m,:] @ (Wh_e + Wl_e) + b_e)
// Virtual K=256 per expert: [A|A] x [Bh|Bl]. Warp tile 32x64 (m16n8k16).
__global__ void __launch_bounds__(256, 1)
moe_hmma_kernel(const __half* __restrict__ A, const __half* __restrict__ wprepL,
                const float* __restrict__ bias, const float* __restrict__ gate,
                float* __restrict__ out, __half* __restrict__ outh, int n)
{
    extern __shared__ char smem[];
    const uint32_t sb = smem_u32(smem);
    const int t = threadIdx.x, lane = t & 31, wid = t >> 5;
    const int row0 = blockIdx.x * 128;
    float* sBias = (float*)(smem + 5 * IMG_B);

    for (int i = t; i < NEXP * FD; i += 256) sBias[i] = bias[i];

    // A tile: async copy fp16 rows (256B data) into padded image (272B stride)
    #pragma unroll
    for (int i = 0; i < 8; i++) {
        int id = i * 256 + t;                // 0..2047 chunks of 16B
        int r = id >> 4, chunk = id & 15;
        int gr = row0 + r;
        uint32_t dst = sb + (uint32_t)r * ROWSTRIDE + (uint32_t)chunk * 16;
        const void* src = A + ((size_t)gr * 128 + chunk * 8);
        cpa16z(dst, src, (gr < n) ? 16 : 0);
    }
    // prefetch expert-0 B (hi+lo = 2 images contiguous) into buf0
    {
        uint32_t dst = sb + IMG_B;
        const char* src = (const char*)wprepL;
        for (int i = t; i < 2 * IMG_B / 16; i += 256) cpa16(dst + i * 16, src + i * 16);
    }
    CP_COMMIT();
    CP_WAIT0();
    __syncthreads();

    const int m0 = (wid & 3) * 32, n0 = (wid >> 2) * 64;
    uint32_t aoff[2];
    #pragma unroll
    for (int mt = 0; mt < 2; mt++)
        aoff[mt] = (uint32_t)((m0 + mt * 16 + (lane & 7) + ((lane >> 3) & 1) * 8) * ROWSTRIDE
                              + (lane >> 4) * 16);
    const int l16 = lane & 15;
    uint32_t boff[8];
    #pragma unroll
    for (int nt = 0; nt < 8; nt++)
        boff[nt] = (uint32_t)((n0 + nt * 8 + (l16 & 7)) * ROWSTRIDE + (l16 >> 3) * 16);

    float o[2][8][4];
    #pragma unroll
    for (int mt = 0; mt < 2; mt++)
        #pragma unroll
        for (int nt = 0; nt < 8; nt++)
            #pragma unroll
            for (int j = 0; j < 4; j++) o[mt][nt][j] = 0.f;

    for (int e = 0; e < NEXP; e++) {
        const uint32_t bbase = sb + IMG_B + (uint32_t)(e & 1) * 2 * IMG_B;
        if (e < 2) {   // prefetch next expert into the other buffer
            uint32_t dst = sb + IMG_B + (uint32_t)((e + 1) & 1) * 2 * IMG_B;
            const char* src = (const char*)(wprepL + (size_t)(e + 1) * 2 * IMG_ELEMS);
            for (int i = t; i < 2 * IMG_B / 16; i += 256) cpa16(dst + i * 16, src + i * 16);
            CP_COMMIT();
        }

        float c[2][8][4];
        #pragma unroll
        for (int mt = 0; mt < 2; mt++)
            #pragma unroll
            for (int nt = 0; nt < 8; nt++)
                #pragma unroll
                for (int j = 0; j < 4; j++) c[mt][nt][j] = 0.f;

        #pragma unroll 4
        for (int ks = 0; ks < 16; ks++) {
            int term = ks >> 3;                         // 0: Wh, 1: Wl
            uint32_t kb = (uint32_t)((ks & 7) * 32);    // 16 fp16 = 32B
            uint32_t abase = sb + kb;                   // single A image
            uint32_t bbs   = bbase + (term ? IMG_B : 0u) + kb;
            uint32_t a[2][4], b[8][2];
            #pragma unroll
            for (int mt = 0; mt < 2; mt++) ldsm_x4(a[mt], abase + aoff[mt]);
            #pragma unroll
            for (int nt = 0; nt < 8; nt++) ldsm_x2(b[nt], bbs + boff[nt]);
            #pragma unroll
            for (int mt = 0; mt < 2; mt++)
                #pragma unroll
                for (int nt = 0; nt < 8; nt++) mma_f16(c[mt][nt], a[mt], b[nt]);
        }

        // gated relu epilogue into o
        #pragma unroll
        for (int mt = 0; mt < 2; mt++) {
            int r0 = row0 + m0 + mt * 16 + (lane >> 2);
            int r1 = r0 + 8;
            float g0 = (r0 < n) ? gate[r0 * 3 + e] : 0.f;
            float g1 = (r1 < n) ? gate[r1 * 3 + e] : 0.f;
            #pragma unroll
            for (int nt = 0; nt < 8; nt++) {
                int nc = n0 + nt * 8 + 2 * (lane & 3);
                float b0v = sBias[e * 128 + nc], b1v = sBias[e * 128 + nc + 1];
                o[mt][nt][0] = fmaf(g0, fmaxf(c[mt][nt][0] + b0v, 0.f), o[mt][nt][0]);
                o[mt][nt][1] = fmaf(g0, fmaxf(c[mt][nt][1] + b1v, 0.f), o[mt][nt][1]);
                o[mt][nt][2] = fmaf(g1, fmaxf(c[mt][nt][2] + b0v, 0.f), o[mt][nt][2]);
                o[mt][nt][3] = fmaf(g1, fmaxf(c[mt][nt][3] + b1v, 0.f), o[mt][nt][3]);
            }
        }
        if (e < 2) CP_WAIT0();
        __syncthreads();
    }

    #pragma unroll
    for (int mt = 0; mt < 2; mt++) {
        int r0 = row0 + m0 + mt * 16 + (lane >> 2);
        int r1 = r0 + 8;
        #pragma unroll
        for (int nt = 0; nt < 8; nt++) {
            int nc = n0 + nt * 8 + 2 * (lane & 3);
            if (r0 < n) {
                if (out)
                    *(float2*)(out + (size_t)r0 * 128 + nc) = make_float2(o[mt][nt][0], o[mt][nt][1]);
                if (outh)
                    *(__half2*)(outh + (size_t)r0 * 128 + nc) = __floats2half2_rn(o[mt][nt][0], o[mt][nt][1]);
            }
            if (r1 < n) {
                if (out)
                    *(float2*)(out + (size_t)r1 * 128 + nc) = make_float2(o[mt][nt][2], o[mt][nt][3]);
                if (outh)
                    *(__half2*)(outh + (size_t)r1 * 128 + nc) = __floats2half2_rn(o[mt][nt][2], o[mt][nt][3]);
            }
        }
    }
}

// ---------------- fused pool + final (batch is sorted) ----------------
__device__ __forceinline__ int lbound_batch(const void* b, int n, long long key) {
    int lo = 0, hi = n;
    while (lo < hi) {
        int m = (lo + hi) >> 1;
        long long v = g_is64 ? ((const long long*)b)[m] : (long long)((const int*)b)[m];
        if (v < key) lo = m + 1; else hi = m;
    }
    return lo;
}

__global__ void pool_final_kernel(const float* __restrict__ h, const void* batch,
                                  const float* __restrict__ Wf,
                                  const float* __restrict__ bf,
                                  float* __restrict__ outp, int n) {
    __shared__ float sp[128];
    __shared__ int sLo, sHi;
    const int g = blockIdx.x, t = threadIdx.x;
    if (t == 0) sLo = lbound_batch(batch, n, g);
    if (t == 1) sHi = lbound_batch(batch, n, g + 1);
    __syncthreads();
    const int lo = sLo, hi = sHi;
    float s = 0.f;
    int r = lo;
    for (; r + 4 <= hi; r += 4) {
        s += h[(size_t)r * 128 + t] + h[(size_t)(r + 1) * 128 + t] +
             h[(size_t)(r + 2) * 128 + t] + h[(size_t)(r + 3) * 128 + t];
    }
    for (; r < hi; r++) s += h[(size_t)r * 128 + t];
    sp[t] = s / fmaxf((float)(hi - lo), 1.0f);
    __syncthreads();
    if (t < OUTD) {
        float acc = bf[t];
        #pragma unroll
        for (int k = 0; k < 128; k++) acc = fmaf(sp[k], Wf[k * OUTD + t], acc);
        outp[g * OUTD + t] = acc;
    }
}

// ---------------- launcher ----------------
extern "C" void kernel_launch(void* const* d_in, const int* in_sizes, int n_in,
                              void* d_out, int out_size) {
    const float* x    = (const float*)d_in[0];
    const float* top  = (const float*)d_in[1];
    const void*  ei   = d_in[2];
    const void*  batch= d_in[3];
    const float* W0   = (const float*)d_in[4];
    const float* b0   = (const float*)d_in[5];
    const float* Wg0  = (const float*)d_in[6];
    const float* W1   = (const float*)d_in[7];
    const float* b1   = (const float*)d_in[8];
    const float* Wg1  = (const float*)d_in[9];
    const float* Wf   = (const float*)d_in[10];
    const float* bf   = (const float*)d_in[11];
    float* out = (float*)d_out;

    const int N = in_sizes[0] / FD;
    const int E = in_sizes[2] / 2;

    // Device addresses for symbols passed as kernel args (R1 lesson: ATS makes
    // host-shadow symbol reads silently return host zeros).
    float* bufB;  cudaGetSymbolAddress((void**)&bufB,  g_bufB);
    float* gate0; cudaGetSymbolAddress((void**)&gate0, g_gate0);
    float* gate1; cudaGetSymbolAddress((void**)&gate1, g_gate1);
    __half* hh;   cudaGetSymbolAddress((void**)&hh,    g_hh);
    __half* ah;   cudaGetSymbolAddress((void**)&ah,    g_ah);
    __half* wprep; cudaGetSymbolAddress((void**)&wprep, g_wprep);

    cudaFuncSetAttribute(moe_hmma_kernel, cudaFuncAttributeMaxDynamicSharedMemorySize, MOE_SMEM);

    const int TPB = 256;
    int nb_n    = (N + TPB - 1) / TPB;
    int nb_e    = (E + TPB - 1) / TPB;
    int nb_aw   = (N * 32 + TPB - 1) / TPB;   // warp per row
    int nb_moe  = (N + 127) / 128;
    int nb_scan = (N + SCAN_B - 1) / SCAN_B;  // <= SCAN_NBLK
    int nb_x    = (N * 32 + TPB - 1) / TPB;   // x->fp16 conversion blocks

    // fused prep: zero degrees | split weights(fp16) | detect idx width | x->fp16
    prep0_kernel<<<nb_n + 6 + nb_x, TPB>>>((const int*)ei, x, W0, W1, N, nb_n);
    deg_count_kernel<<<nb_e, TPB>>>(ei, E);
    scan_reduce_kernel<<<nb_scan, SCAN_B>>>(N);
    scan_apply_kernel<<<nb_scan, SCAN_B>>>(top, Wg0, Wg1, N, nb_scan);  // + dinv + gates
    scatter_kernel<<<nb_e, TPB>>>(ei, E);

    // layer 0: agg (fp16 in/out); moe emits fp16 image only (feeds layer-1 agg)
    agg_csr_half_kernel<<<nb_aw, TPB>>>(hh, ah, N);
    moe_hmma_kernel<<<nb_moe, TPB, MOE_SMEM>>>(ah, wprep, b0, gate0, nullptr, hh, N);
    // layer 1: agg (fp16 in/out); moe emits fp32 (feeds pooling)
    agg_csr_half_kernel<<<nb_aw, TPB>>>(hh, ah, N);
    moe_hmma_kernel<<<nb_moe, TPB, MOE_SMEM>>>(ah, wprep + 3 * 2 * IMG_ELEMS, b1, gate1,
                                               bufB, nullptr, N);

    // fused pooling + final projection
    pool_final_kernel<<<GG, 128>>>(bufB, batch, Wf, bf, out, N);
}

// round 14
// speedup vs baseline: 1.3539x; 1.1594x over previous
#include <cuda_runtime.h>
#include <cuda_fp16.h>
#include <cstdint>

// Problem constants (from reference)
#define NN      50000
#define EE      800000
#define FD      128
#define GG      64
#define OUTD    64
#define NEXP    3
#define TEMP_F  101.0f

// HMMA MoE config: padded fp16 images, 128 rows x 136 cols (stride 272B)
#define IMG_ELEMS 17408            // 128*136
#define IMG_B     34816            // bytes per image
#define ROWSTRIDE 272              // bytes per row
// smem: A(1 img) | Bbuf0 | Bbuf1 | bias[384]
#define MOE_SMEM  (3 * IMG_B + 1536)

#define SCAN_B    1024
#define SCAN_NBLK 64               // covers up to 65536 nodes

// ---------------- device scratch (no cudaMalloc allowed) ----------------
__device__ float g_dinv[NN];
__device__ int   g_degE[NN];          // in-edge count (no self loop)
__device__ int   g_fill[NN];
__device__ int   g_off[NN + 1];       // CSR row offsets
__device__ int   g_csr[EE];           // CSR src indices
__device__ int   g_bsum[SCAN_NBLK];   // per-block sums for scan
__device__ float g_gate0[NN * NEXP];
__device__ float g_gate1[NN * NEXP];
__device__ __half g_ah[NN * FD];      // fp16 aggregated features (moe A input)
__device__ float g_bufB[NN * FD];     // fp32 layer-1 output (pool input)
__device__ __half g_hh[NN * FD];      // fp16 gather image (x, then h1)
__device__ int   g_is64;
// fp16 weights: [layer(2)][expert(3)][128*136] (padded row-major [n][k])
__device__ __half g_wprep[2 * 3 * IMG_ELEMS];

// ---------------- helpers ----------------
__device__ __forceinline__ uint32_t smem_u32(const void* p) {
    uint32_t a;
    asm("{ .reg .u64 t; cvta.to.shared.u64 t, %1; cvt.u32.u64 %0, t; }" : "=r"(a) : "l"(p));
    return a;
}
__device__ __forceinline__ int load_idx(const void* p, long long i) {
    if (g_is64) return (int)((const long long*)p)[i];
    return ((const int*)p)[i];
}
__device__ __forceinline__ void cpa16(uint32_t dst, const void* src) {
    asm volatile("cp.async.cg.shared.global [%0], [%1], 16;" :: "r"(dst), "l"(src) : "memory");
}
// cp.async with runtime src-size (0 => full zero-fill)
__device__ __forceinline__ void cpa16z(uint32_t dst, const void* src, int sz) {
    asm volatile("cp.async.cg.shared.global [%0], [%1], 16, %2;"
                 :: "r"(dst), "l"(src), "r"(sz) : "memory");
}
#define CP_COMMIT() asm volatile("cp.async.commit_group;" ::: "memory")
#define CP_WAIT0()  asm volatile("cp.async.wait_group 0;" ::: "memory")

__device__ __forceinline__ void ldsm_x4(uint32_t (&r)[4], uint32_t addr) {
    asm volatile("ldmatrix.sync.aligned.m8n8.x4.shared.b16 {%0,%1,%2,%3}, [%4];"
                 : "=r"(r[0]), "=r"(r[1]), "=r"(r[2]), "=r"(r[3]) : "r"(addr));
}
__device__ __forceinline__ void ldsm_x2(uint32_t (&r)[2], uint32_t addr) {
    asm volatile("ldmatrix.sync.aligned.m8n8.x2.shared.b16 {%0,%1}, [%2];"
                 : "=r"(r[0]), "=r"(r[1]) : "r"(addr));
}
__device__ __forceinline__ void mma_f16(float (&c)[4], const uint32_t (&a)[4],
                                        const uint32_t (&b)[2]) {
    asm volatile("mma.sync.aligned.m16n8k16.row.col.f32.f16.f16.f32 "
                 "{%0,%1,%2,%3}, {%4,%5,%6,%7}, {%8,%9}, {%0,%1,%2,%3};"
                 : "+f"(c[0]), "+f"(c[1]), "+f"(c[2]), "+f"(c[3])
                 : "r"(a[0]), "r"(a[1]), "r"(a[2]), "r"(a[3]), "r"(b[0]), "r"(b[1]));
}
__device__ __forceinline__ float4 h4_to_f4(uint2 u) {
    __half2 a = *reinterpret_cast<__half2*>(&u.x);
    __half2 b = *reinterpret_cast<__half2*>(&u.y);
    float2 fa = __half22float2(a), fb = __half22float2(b);
    return make_float4(fa.x, fa.y, fb.x, fb.y);
}

// ---------------- fused prep0: deg zero | weight cvt(fp16) | detect | x->fp16 ----------------
__global__ void prep0_kernel(const int* eip, const float* __restrict__ x,
                             const float* __restrict__ W0,
                             const float* __restrict__ W1, int n, int nbn) {
    if ((int)blockIdx.x < nbn) {
        int i = blockIdx.x * blockDim.x + threadIdx.x;
        if (i < n) { g_degE[i] = 0; g_fill[i] = 0; }
        if (blockIdx.x == 0 && threadIdx.x == 0) {
            int all0 = 1;
            #pragma unroll
            for (int k = 1; k < 128; k += 2) if (eip[k] != 0) all0 = 0;
            g_is64 = all0;
        }
        return;
    }
    if ((int)blockIdx.x < nbn + 6) {
        int b = blockIdx.x - nbn;                   // 0..5 = layer*3+expert
        const float* src = (b < 3 ? W0 : W1) + (b % 3) * (FD * FD);
        __half* dst = g_wprep + (size_t)b * IMG_ELEMS;
        for (int i = threadIdx.x; i < FD * FD; i += blockDim.x) {
            int nidx = i >> 7, k = i & 127;
            dst[nidx * 136 + k] = __float2half_rn(src[k * FD + nidx]);
        }
        return;
    }
    // x -> fp16 gather image
    int id = (blockIdx.x - nbn - 6) * blockDim.x + threadIdx.x;  // float4 index
    if (id < n * 32) {
        float4 v = reinterpret_cast<const float4*>(x)[id];
        uint2 u;
        *reinterpret_cast<__half2*>(&u.x) = __floats2half2_rn(v.x, v.y);
        *reinterpret_cast<__half2*>(&u.y) = __floats2half2_rn(v.z, v.w);
        reinterpret_cast<uint2*>(g_hh)[id] = u;
    }
}

__global__ void deg_count_kernel(const void* ei, int E) {
    int i = blockIdx.x * blockDim.x + threadIdx.x;
    if (i >= E) return;
    atomicAdd(&g_degE[load_idx(ei, (long long)E + i)], 1);
}

// ---- scan phase 1: per-block sums ----
__global__ void __launch_bounds__(SCAN_B, 1) scan_reduce_kernel(int n) {
    __shared__ int sred[32];
    int i = blockIdx.x * SCAN_B + threadIdx.x;
    int v = (i < n) ? g_degE[i] : 0;
    #pragma unroll
    for (int o = 16; o > 0; o >>= 1) v += __shfl_down_sync(0xFFFFFFFFu, v, o);
    if ((threadIdx.x & 31) == 0) sred[threadIdx.x >> 5] = v;
    __syncthreads();
    if (threadIdx.x < 32) {
        int w = (threadIdx.x < SCAN_B / 32) ? sred[threadIdx.x] : 0;
        #pragma unroll
        for (int o = 16; o > 0; o >>= 1) w += __shfl_down_sync(0xFFFFFFFFu, w, o);
        if (threadIdx.x == 0) g_bsum[blockIdx.x] = w;
    }
}

// ---- scan phase 2 (fat): block-sum scan + elementwise scan + dinv + gates ----
__global__ void __launch_bounds__(SCAN_B, 1)
scan_apply_kernel(const float* __restrict__ top, const float* __restrict__ Wg0,
                  const float* __restrict__ Wg1, int n, int nblk) {
    __shared__ int swarp[32];
    __shared__ int sbs[SCAN_NBLK];
    const int t = threadIdx.x;
    if (t < SCAN_NBLK) sbs[t] = (t < nblk) ? g_bsum[t] : 0;
    __syncthreads();
    #pragma unroll
    for (int o = 1; o < SCAN_NBLK; o <<= 1) {
        int u = (t >= o && t < SCAN_NBLK) ? sbs[t - o] : 0;
        __syncthreads();
        if (t < SCAN_NBLK) sbs[t] += u;
        __syncthreads();
    }
    const int blockbase = (blockIdx.x == 0) ? 0 : sbs[blockIdx.x - 1];

    int i = blockIdx.x * SCAN_B + t;
    int lane = t & 31, wid = t >> 5;
    int v = (i < n) ? g_degE[i] : 0;
    int inc = v;
    #pragma unroll
    for (int o = 1; o < 32; o <<= 1) {
        int u = __shfl_up_sync(0xFFFFFFFFu, inc, o);
        if (lane >= o) inc += u;
    }
    if (lane == 31) swarp[wid] = inc;
    __syncthreads();
    if (wid == 0) {
        int w = (lane < SCAN_B / 32) ? swarp[lane] : 0;
        int winc = w;
        #pragma unroll
        for (int o = 1; o < 32; o <<= 1) {
            int u = __shfl_up_sync(0xFFFFFFFFu, winc, o);
            if (lane >= o) winc += u;
        }
        swarp[lane] = winc - w;
    }
    __syncthreads();
    int base = blockbase + swarp[wid];
    if (i < n) {
        g_off[i] = base + inc - v;
        if (i == n - 1) g_off[n] = base + inc;

        g_dinv[i] = rsqrtf((float)(v + 1));
        float t0 = top[i * 4 + 0], t1 = top[i * 4 + 1];
        float t2 = top[i * 4 + 2], t3 = top[i * 4 + 3];
        const float* wgs[2] = {Wg0, Wg1};
        float* outs[2] = {g_gate0, g_gate1};
        #pragma unroll
        for (int L = 0; L < 2; L++) {
            const float* Wg = wgs[L];
            float l[NEXP];
            #pragma unroll
            for (int e = 0; e < NEXP; e++)
                l[e] = (t0 * Wg[e * 4 + 0] + t1 * Wg[e * 4 + 1] +
                        t2 * Wg[e * 4 + 2] + t3 * Wg[e * 4 + 3]) * (1.0f / TEMP_F);
            float m = fmaxf(l[0], fmaxf(l[1], l[2]));
            float e0 = __expf(l[0] - m), e1 = __expf(l[1] - m), e2 = __expf(l[2] - m);
            float inv = 1.0f / (e0 + e1 + e2);
            outs[L][i * 3 + 0] = e0 * inv;
            outs[L][i * 3 + 1] = e1 * inv;
            outs[L][i * 3 + 2] = e2 * inv;
        }
    }
}

__global__ void scatter_kernel(const void* ei, int E) {
    int i = blockIdx.x * blockDim.x + threadIdx.x;
    if (i >= E) return;
    int s = load_idx(ei, i);
    int d = load_idx(ei, (long long)E + i);
    int pos = g_off[d] + atomicAdd(&g_fill[d], 1);
    g_csr[pos] = s;
}

// ---------------- CSR aggregation from fp16 image (no atomics), fp16 out ----------------
__global__ void agg_csr_half_kernel(const __half* __restrict__ hhv,
                                    __half* __restrict__ out, int n) {
    int r = (blockIdx.x * blockDim.x + threadIdx.x) >> 5;
    int lane = threadIdx.x & 31;
    if (r >= n) return;
    const uint2* hp = (const uint2*)hhv;     // 4 halves per uint2; 32 per row
    float di = g_dinv[r];
    float4 self = h4_to_f4(hp[(size_t)r * 32 + lane]);
    float s2 = di * di;
    float4 acc = make_float4(s2 * self.x, s2 * self.y, s2 * self.z, s2 * self.w);
    int e = g_off[r], e1 = g_off[r + 1];
    for (; e + 2 <= e1; e += 2) {
        int s0 = g_csr[e], s1 = g_csr[e + 1];
        float n0 = di * g_dinv[s0], n1 = di * g_dinv[s1];
        float4 v0 = h4_to_f4(hp[(size_t)s0 * 32 + lane]);
        float4 v1 = h4_to_f4(hp[(size_t)s1 * 32 + lane]);
        acc.x = fmaf(n0, v0.x, fmaf(n1, v1.x, acc.x));
        acc.y = fmaf(n0, v0.y, fmaf(n1, v1.y, acc.y));
        acc.z = fmaf(n0, v0.z, fmaf(n1, v1.z, acc.z));
        acc.w = fmaf(n0, v0.w, fmaf(n1, v1.w, acc.w));
    }
    if (e < e1) {
        int s0 = g_csr[e];
        float n0 = di * g_dinv[s0];
        float4 v0 = h4_to_f4(hp[(size_t)s0 * 32 + lane]);
        acc.x = fmaf(n0, v0.x, acc.x);
        acc.y = fmaf(n0, v0.y, acc.y);
        acc.z = fmaf(n0, v0.z, acc.z);
        acc.w = fmaf(n0, v0.w, acc.w);
    }
    uint2 uo;
    *reinterpret_cast<__half2*>(&uo.x) = __floats2half2_rn(acc.x, acc.y);
    *reinterpret_cast<__half2*>(&uo.y) = __floats2half2_rn(acc.z, acc.w);
    ((uint2*)out)[(size_t)r * 32 + lane] = uo;
}

// ---------------- HMMA MoE layer: fp16 A, fp16 W (single term) ----------------
// out[m,:] = sum_e gate[m,e]*relu(A[m,:] @ W_e + b_e). K=8 mma steps per expert.
__global__ void __launch_bounds__(256, 1)
moe_hmma_kernel(const __half* __restrict__ A, const __half* __restrict__ wprepL,
                const float* __restrict__ bias, const float* __restrict__ gate,
                float* __restrict__ out, __half* __restrict__ outh, int n)
{
    extern __shared__ char smem[];
    const uint32_t sb = smem_u32(smem);
    const int t = threadIdx.x, lane = t & 31, wid = t >> 5;
    const int row0 = blockIdx.x * 128;
    float* sBias = (float*)(smem + 3 * IMG_B);

    for (int i = t; i < NEXP * FD; i += 256) sBias[i] = bias[i];

    // A tile: async copy fp16 rows (256B data) into padded image (272B stride)
    #pragma unroll
    for (int i = 0; i < 8; i++) {
        int id = i * 256 + t;                // 0..2047 chunks of 16B
        int r = id >> 4, chunk = id & 15;
        int gr = row0 + r;
        uint32_t dst = sb + (uint32_t)r * ROWSTRIDE + (uint32_t)chunk * 16;
        const void* src = A + ((size_t)gr * 128 + chunk * 8);
        cpa16z(dst, src, (gr < n) ? 16 : 0);
    }
    // prefetch expert-0 B image into buf0
    {
        uint32_t dst = sb + IMG_B;
        const char* src = (const char*)wprepL;
        for (int i = t; i < IMG_B / 16; i += 256) cpa16(dst + i * 16, src + i * 16);
    }
    CP_COMMIT();
    CP_WAIT0();
    __syncthreads();

    const int m0 = (wid & 3) * 32, n0 = (wid >> 2) * 64;
    uint32_t aoff[2];
    #pragma unroll
    for (int mt = 0; mt < 2; mt++)
        aoff[mt] = (uint32_t)((m0 + mt * 16 + (lane & 7) + ((lane >> 3) & 1) * 8) * ROWSTRIDE
                              + (lane >> 4) * 16);
    const int l16 = lane & 15;
    uint32_t boff[8];
    #pragma unroll
    for (int nt = 0; nt < 8; nt++)
        boff[nt] = (uint32_t)((n0 + nt * 8 + (l16 & 7)) * ROWSTRIDE + (l16 >> 3) * 16);

    float o[2][8][4];
    #pragma unroll
    for (int mt = 0; mt < 2; mt++)
        #pragma unroll
        for (int nt = 0; nt < 8; nt++)
            #pragma unroll
            for (int j = 0; j < 4; j++) o[mt][nt][j] = 0.f;

    for (int e = 0; e < NEXP; e++) {
        const uint32_t bbase = sb + IMG_B + (uint32_t)(e & 1) * IMG_B;
        if (e < 2) {   // prefetch next expert into the other buffer
            uint32_t dst = sb + IMG_B + (uint32_t)((e + 1) & 1) * IMG_B;
            const char* src = (const char*)(wprepL + (size_t)(e + 1) * IMG_ELEMS);
            for (int i = t; i < IMG_B / 16; i += 256) cpa16(dst + i * 16, src + i * 16);
            CP_COMMIT();
        }

        float c[2][8][4];
        #pragma unroll
        for (int mt = 0; mt < 2; mt++)
            #pragma unroll
            for (int nt = 0; nt < 8; nt++)
                #pragma unroll
                for (int j = 0; j < 4; j++) c[mt][nt][j] = 0.f;

        #pragma unroll
        for (int ks = 0; ks < 8; ks++) {
            uint32_t kb = (uint32_t)(ks * 32);          // 16 fp16 = 32B
            uint32_t abase = sb + kb;
            uint32_t bbs   = bbase + kb;
            uint32_t a[2][4], b[8][2];
            #pragma unroll
            for (int mt = 0; mt < 2; mt++) ldsm_x4(a[mt], abase + aoff[mt]);
            #pragma unroll
            for (int nt = 0; nt < 8; nt++) ldsm_x2(b[nt], bbs + boff[nt]);
            #pragma unroll
            for (int mt = 0; mt < 2; mt++)
                #pragma unroll
                for (int nt = 0; nt < 8; nt++) mma_f16(c[mt][nt], a[mt], b[nt]);
        }

        // gated relu epilogue into o
        #pragma unroll
        for (int mt = 0; mt < 2; mt++) {
            int r0 = row0 + m0 + mt * 16 + (lane >> 2);
            int r1 = r0 + 8;
            float g0 = (r0 < n) ? gate[r0 * 3 + e] : 0.f;
            float g1 = (r1 < n) ? gate[r1 * 3 + e] : 0.f;
            #pragma unroll
            for (int nt = 0; nt < 8; nt++) {
                int nc = n0 + nt * 8 + 2 * (lane & 3);
                float b0v = sBias[e * 128 + nc], b1v = sBias[e * 128 + nc + 1];
                o[mt][nt][0] = fmaf(g0, fmaxf(c[mt][nt][0] + b0v, 0.f), o[mt][nt][0]);
                o[mt][nt][1] = fmaf(g0, fmaxf(c[mt][nt][1] + b1v, 0.f), o[mt][nt][1]);
                o[mt][nt][2] = fmaf(g1, fmaxf(c[mt][nt][2] + b0v, 0.f), o[mt][nt][2]);
                o[mt][nt][3] = fmaf(g1, fmaxf(c[mt][nt][3] + b1v, 0.f), o[mt][nt][3]);
            }
        }
        if (e < 2) CP_WAIT0();
        __syncthreads();
    }

    #pragma unroll
    for (int mt = 0; mt < 2; mt++) {
        int r0 = row0 + m0 + mt * 16 + (lane >> 2);
        int r1 = r0 + 8;
        #pragma unroll
        for (int nt = 0; nt < 8; nt++) {
            int nc = n0 + nt * 8 + 2 * (lane & 3);
            if (r0 < n) {
                if (out)
                    *(float2*)(out + (size_t)r0 * 128 + nc) = make_float2(o[mt][nt][0], o[mt][nt][1]);
                if (outh)
                    *(__half2*)(outh + (size_t)r0 * 128 + nc) = __floats2half2_rn(o[mt][nt][0], o[mt][nt][1]);
            }
            if (r1 < n) {
                if (out)
                    *(float2*)(out + (size_t)r1 * 128 + nc) = make_float2(o[mt][nt][2], o[mt][nt][3]);
                if (outh)
                    *(__half2*)(outh + (size_t)r1 * 128 + nc) = __floats2half2_rn(o[mt][nt][2], o[mt][nt][3]);
            }
        }
    }
}

// ---------------- fused pool + final (batch is sorted) ----------------
__device__ __forceinline__ int lbound_batch(const void* b, int n, long long key) {
    int lo = 0, hi = n;
    while (lo < hi) {
        int m = (lo + hi) >> 1;
        long long v = g_is64 ? ((const long long*)b)[m] : (long long)((const int*)b)[m];
        if (v < key) lo = m + 1; else hi = m;
    }
    return lo;
}

__global__ void pool_final_kernel(const float* __restrict__ h, const void* batch,
                                  const float* __restrict__ Wf,
                                  const float* __restrict__ bf,
                                  float* __restrict__ outp, int n) {
    __shared__ float sp[128];
    __shared__ int sLo, sHi;
    const int g = blockIdx.x, t = threadIdx.x;
    if (t == 0) sLo = lbound_batch(batch, n, g);
    if (t == 1) sHi = lbound_batch(batch, n, g + 1);
    __syncthreads();
    const int lo = sLo, hi = sHi;
    float s = 0.f;
    int r = lo;
    for (; r + 4 <= hi; r += 4) {
        s += h[(size_t)r * 128 + t] + h[(size_t)(r + 1) * 128 + t] +
             h[(size_t)(r + 2) * 128 + t] + h[(size_t)(r + 3) * 128 + t];
    }
    for (; r < hi; r++) s += h[(size_t)r * 128 + t];
    sp[t] = s / fmaxf((float)(hi - lo), 1.0f);
    __syncthreads();
    if (t < OUTD) {
        float acc = bf[t];
        #pragma unroll
        for (int k = 0; k < 128; k++) acc = fmaf(sp[k], Wf[k * OUTD + t], acc);
        outp[g * OUTD + t] = acc;
    }
}

// ---------------- launcher ----------------
extern "C" void kernel_launch(void* const* d_in, const int* in_sizes, int n_in,
                              void* d_out, int out_size) {
    const float* x    = (const float*)d_in[0];
    const float* top  = (const float*)d_in[1];
    const void*  ei   = d_in[2];
    const void*  batch= d_in[3];
    const float* W0   = (const float*)d_in[4];
    const float* b0   = (const float*)d_in[5];
    const float* Wg0  = (const float*)d_in[6];
    const float* W1   = (const float*)d_in[7];
    const float* b1   = (const float*)d_in[8];
    const float* Wg1  = (const float*)d_in[9];
    const float* Wf   = (const float*)d_in[10];
    const float* bf   = (const float*)d_in[11];
    float* out = (float*)d_out;

    const int N = in_sizes[0] / FD;
    const int E = in_sizes[2] / 2;

    // Device addresses for symbols passed as kernel args (R1 lesson: ATS makes
    // host-shadow symbol reads silently return host zeros).
    float* bufB;  cudaGetSymbolAddress((void**)&bufB,  g_bufB);
    float* gate0; cudaGetSymbolAddress((void**)&gate0, g_gate0);
    float* gate1; cudaGetSymbolAddress((void**)&gate1, g_gate1);
    __half* hh;   cudaGetSymbolAddress((void**)&hh,    g_hh);
    __half* ah;   cudaGetSymbolAddress((void**)&ah,    g_ah);
    __half* wprep; cudaGetSymbolAddress((void**)&wprep, g_wprep);

    cudaFuncSetAttribute(moe_hmma_kernel, cudaFuncAttributeMaxDynamicSharedMemorySize, MOE_SMEM);

    const int TPB = 256;
    int nb_n    = (N + TPB - 1) / TPB;
    int nb_e    = (E + TPB - 1) / TPB;
    int nb_aw   = (N * 32 + TPB - 1) / TPB;   // warp per row
    int nb_moe  = (N + 127) / 128;
    int nb_scan = (N + SCAN_B - 1) / SCAN_B;  // <= SCAN_NBLK
    int nb_x    = (N * 32 + TPB - 1) / TPB;   // x->fp16 conversion blocks

    // fused prep: zero degrees | cvt weights(fp16) | detect idx width | x->fp16
    prep0_kernel<<<nb_n + 6 + nb_x, TPB>>>((const int*)ei, x, W0, W1, N, nb_n);
    deg_count_kernel<<<nb_e, TPB>>>(ei, E);
    scan_reduce_kernel<<<nb_scan, SCAN_B>>>(N);
    scan_apply_kernel<<<nb_scan, SCAN_B>>>(top, Wg0, Wg1, N, nb_scan);  // + dinv + gates
    scatter_kernel<<<nb_e, TPB>>>(ei, E);

    // layer 0: agg (fp16 in/out); moe emits fp16 image only (feeds layer-1 agg)
    agg_csr_half_kernel<<<nb_aw, TPB>>>(hh, ah, N);
    moe_hmma_kernel<<<nb_moe, TPB, MOE_SMEM>>>(ah, wprep, b0, gate0, nullptr, hh, N);
    // layer 1: agg (fp16 in/out); moe emits fp32 (feeds pooling)
    agg_csr_half_kernel<<<nb_aw, TPB>>>(hh, ah, N);
    moe_hmma_kernel<<<nb_moe, TPB, MOE_SMEM>>>(ah, wprep + 3 * IMG_ELEMS, b1, gate1,
                                               bufB, nullptr, N);

    // fused pooling + final projection
    pool_final_kernel<<<GG, 128>>>(bufB, batch, Wf, bf, out, N);
}